// round 2
// baseline (speedup 1.0000x reference)
#include <cuda_runtime.h>
#include <math.h>

// Problem constants
#define NB 128
#define NI 1152
#define NO 32
#define ND 16
#define KSUB 922          // ceil(0.8 * 1152)
#define CHUNKS 9
#define IPB (NI / CHUNKS) // 128 i's per block
#define IPW (IPB / 8)     // 16 i's per warp (8 warps / block)
#define SORTN 2048        // next pow2 >= NI

// Scratch (no allocation allowed -> __device__ globals)
__device__ float g_num[NB * NO * ND];
__device__ float g_den[NB * NO];
__device__ float g_v[NB * NO * ND];
__device__ float g_num2[NB * NO * ND];
__device__ float g_den2[NB * NO];
__device__ float g_losses[(size_t)NB * NI * NO];
__device__ float g_thresh[NB * NO];

__global__ void k_zero() {
    int idx = blockIdx.x * blockDim.x + threadIdx.x;
    if (idx < NB * NO * ND) { g_num[idx] = 0.f; g_num2[idx] = 0.f; }
    if (idx < NB * NO)      { g_den[idx] = 0.f; g_den2[idx] = 0.f; }
}

// ---------------------------------------------------------------------------
// Pass 1: n = ||u||, num = sum_i u*n, den = sum_i n  (per b,o)
// One warp per (b,i); lane = o. Each lane reads its 64B capsule (4x LDG.128).
// ---------------------------------------------------------------------------
__global__ void __launch_bounds__(256) k_pass1(const float* __restrict__ u) {
    int b = blockIdx.x / CHUNKS;
    int chunk = blockIdx.x % CHUNKS;
    int w = threadIdx.x >> 5;
    int lane = threadIdx.x & 31;

    const float4* up = (const float4*)u + (size_t)b * NI * (NO * ND / 4);
    float acc[ND];
    float accden = 0.f;
#pragma unroll
    for (int d = 0; d < ND; d++) acc[d] = 0.f;

    int i0 = chunk * IPB + w * IPW;
    for (int ii = 0; ii < IPW; ii++) {
        const float4* row = up + (size_t)(i0 + ii) * (NO * ND / 4) + lane * (ND / 4);
        float4 a0 = row[0], a1 = row[1], a2 = row[2], a3 = row[3];
        float va[16] = {a0.x, a0.y, a0.z, a0.w, a1.x, a1.y, a1.z, a1.w,
                        a2.x, a2.y, a2.z, a2.w, a3.x, a3.y, a3.z, a3.w};
        float s = 0.f;
#pragma unroll
        for (int d = 0; d < 16; d++) s += va[d] * va[d];
        float n = sqrtf(s);
#pragma unroll
        for (int d = 0; d < 16; d++) acc[d] += va[d] * n;
        accden += n;
    }

    // Block reduction. Transposed smem layout [d][o] -> conflict-free stores.
    __shared__ float snum[8][NO * ND];
    __shared__ float sden[8][NO];
#pragma unroll
    for (int d = 0; d < ND; d++) snum[w][d * NO + lane] = acc[d];
    sden[w][lane] = accden;
    __syncthreads();

    for (int idx = threadIdx.x; idx < NO * ND; idx += 256) {
        int d = idx / NO, o = idx % NO;
        float s = 0.f;
#pragma unroll
        for (int ww = 0; ww < 8; ww++) s += snum[ww][idx];
        atomicAdd(&g_num[b * NO * ND + o * ND + d], s);
    }
    if (threadIdx.x < NO) {
        float s = 0.f;
#pragma unroll
        for (int ww = 0; ww < 8; ww++) s += sden[ww][threadIdx.x];
        atomicAdd(&g_den[b * NO + threadIdx.x], s);
    }
}

__global__ void k_divv() {
    int idx = blockIdx.x * blockDim.x + threadIdx.x;
    if (idx < NB * NO * ND) g_v[idx] = g_num[idx] / g_den[idx / ND];
}

// ---------------------------------------------------------------------------
// Pass 2: losses[b,i,o] = -<v[b,o,:], u[b,i,o,:]>
// ---------------------------------------------------------------------------
__global__ void __launch_bounds__(256) k_pass2(const float* __restrict__ u) {
    __shared__ float sv[ND * NO]; // transposed: sv[d*NO + o]
    int b = blockIdx.x / CHUNKS;
    int chunk = blockIdx.x % CHUNKS;
    for (int idx = threadIdx.x; idx < NO * ND; idx += 256) {
        int o = idx / ND, d = idx % ND;
        sv[d * NO + o] = g_v[b * NO * ND + idx];
    }
    __syncthreads();

    int w = threadIdx.x >> 5;
    int lane = threadIdx.x & 31;
    const float4* up = (const float4*)u + (size_t)b * NI * (NO * ND / 4);
    int i0 = chunk * IPB + w * IPW;
    for (int ii = 0; ii < IPW; ii++) {
        int i = i0 + ii;
        const float4* row = up + (size_t)i * (NO * ND / 4) + lane * (ND / 4);
        float4 a0 = row[0], a1 = row[1], a2 = row[2], a3 = row[3];
        float va[16] = {a0.x, a0.y, a0.z, a0.w, a1.x, a1.y, a1.z, a1.w,
                        a2.x, a2.y, a2.z, a2.w, a3.x, a3.y, a3.z, a3.w};
        float dotv = 0.f;
#pragma unroll
        for (int d = 0; d < 16; d++) dotv += sv[d * NO + lane] * va[d];
        g_losses[((size_t)b * NI + i) * NO + lane] = -dotv;
    }
}

// ---------------------------------------------------------------------------
// Selection: per (b,o), k-th smallest of 1152 losses via bitonic sort of 2048
// (padded with +inf). One block per (b,o).
// ---------------------------------------------------------------------------
__global__ void __launch_bounds__(256) k_select() {
    __shared__ float s[SORTN];
    int b = blockIdx.x / NO;
    int o = blockIdx.x % NO;
    const float INF = __int_as_float(0x7f800000);
    for (int idx = threadIdx.x; idx < SORTN; idx += 256)
        s[idx] = (idx < NI) ? g_losses[((size_t)b * NI + idx) * NO + o] : INF;
    __syncthreads();

    for (int k = 2; k <= SORTN; k <<= 1) {
        for (int j = k >> 1; j > 0; j >>= 1) {
            for (int idx = threadIdx.x; idx < SORTN; idx += 256) {
                int ixj = idx ^ j;
                if (ixj > idx) {
                    bool ascend = ((idx & k) == 0);
                    float a = s[idx], c = s[ixj];
                    if ((a > c) == ascend) { s[idx] = c; s[ixj] = a; }
                }
            }
            __syncthreads();
        }
    }
    if (threadIdx.x == 0) g_thresh[blockIdx.x] = s[KSUB - 1];
}

// ---------------------------------------------------------------------------
// Pass 3: masked weighted average. Re-reads stored losses (bit-exact with
// the threshold source) instead of recomputing, to avoid boundary flips.
// ---------------------------------------------------------------------------
__global__ void __launch_bounds__(256) k_pass3(const float* __restrict__ u) {
    __shared__ float sthr[NO];
    int b = blockIdx.x / CHUNKS;
    int chunk = blockIdx.x % CHUNKS;
    if (threadIdx.x < NO) sthr[threadIdx.x] = g_thresh[b * NO + threadIdx.x];
    __syncthreads();

    int w = threadIdx.x >> 5;
    int lane = threadIdx.x & 31;
    const float4* up = (const float4*)u + (size_t)b * NI * (NO * ND / 4);
    float acc[ND];
    float accden = 0.f;
#pragma unroll
    for (int d = 0; d < ND; d++) acc[d] = 0.f;

    float thr = sthr[lane];
    int i0 = chunk * IPB + w * IPW;
    for (int ii = 0; ii < IPW; ii++) {
        int i = i0 + ii;
        const float4* row = up + (size_t)i * (NO * ND / 4) + lane * (ND / 4);
        float4 a0 = row[0], a1 = row[1], a2 = row[2], a3 = row[3];
        float loss = g_losses[((size_t)b * NI + i) * NO + lane];
        if (loss <= thr) {
            float va[16] = {a0.x, a0.y, a0.z, a0.w, a1.x, a1.y, a1.z, a1.w,
                            a2.x, a2.y, a2.z, a2.w, a3.x, a3.y, a3.z, a3.w};
            float ssum = 0.f;
#pragma unroll
            for (int d = 0; d < 16; d++) ssum += va[d] * va[d];
            float n = sqrtf(ssum);
#pragma unroll
            for (int d = 0; d < 16; d++) acc[d] += va[d] * n;
            accden += n;
        }
    }

    __shared__ float snum[8][NO * ND];
    __shared__ float sden[8][NO];
#pragma unroll
    for (int d = 0; d < ND; d++) snum[w][d * NO + lane] = acc[d];
    sden[w][lane] = accden;
    __syncthreads();

    for (int idx = threadIdx.x; idx < NO * ND; idx += 256) {
        int d = idx / NO, o = idx % NO;
        float s = 0.f;
#pragma unroll
        for (int ww = 0; ww < 8; ww++) s += snum[ww][idx];
        atomicAdd(&g_num2[b * NO * ND + o * ND + d], s);
    }
    if (threadIdx.x < NO) {
        float s = 0.f;
#pragma unroll
        for (int ww = 0; ww < 8; ww++) s += sden[ww][threadIdx.x];
        atomicAdd(&g_den2[b * NO + threadIdx.x], s);
    }
}

__global__ void k_out(float* __restrict__ out) {
    int idx = blockIdx.x * blockDim.x + threadIdx.x;
    if (idx < NB * NO * ND) out[idx] = g_num2[idx] / g_den2[idx / ND];
}

extern "C" void kernel_launch(void* const* d_in, const int* in_sizes, int n_in,
                              void* d_out, int out_size) {
    const float* u = (const float*)d_in[0];
    float* out = (float*)d_out;

    k_zero<<<(NB * NO * ND + 255) / 256, 256>>>();
    k_pass1<<<NB * CHUNKS, 256>>>(u);
    k_divv<<<(NB * NO * ND + 255) / 256, 256>>>();
    k_pass2<<<NB * CHUNKS, 256>>>(u);
    k_select<<<NB * NO, 256>>>();
    k_pass3<<<NB * CHUNKS, 256>>>(u);
    k_out<<<(NB * NO * ND + 255) / 256, 256>>>(out);
}

// round 3
// speedup vs baseline: 2.2241x; 2.2241x over previous
#include <cuda_runtime.h>
#include <math.h>

// Problem constants
#define NB 128
#define NI 1152
#define NO 32
#define ND 16
#define KSUB 922          // ceil(0.8 * 1152)
#define CHUNKS 9
#define IPB (NI / CHUNKS) // 128 i's per block
#define IPW (IPB / 8)     // 16 i's per warp (8 warps / block)
#define MAXREJ 232        // >= NI - KSUB = 230

// Scratch (no allocation allowed -> __device__ globals)
__device__ float g_num[NB * NO * ND];
__device__ float g_den[NB * NO];
__device__ float g_losses[(size_t)NB * NO * NI]; // transposed: [b][o][i]

__global__ void k_zero() {
    int idx = blockIdx.x * blockDim.x + threadIdx.x;
    if (idx < NB * NO * ND) g_num[idx] = 0.f;
    if (idx < NB * NO)      g_den[idx] = 0.f;
}

// ---------------------------------------------------------------------------
// Pass 1: n = ||u||, num = sum_i u*n, den = sum_i n  (per b,o)
// One warp per (b,i); lane = o. Each lane reads its 64B capsule (4x LDG.128).
// ---------------------------------------------------------------------------
__global__ void __launch_bounds__(256) k_pass1(const float* __restrict__ u) {
    int b = blockIdx.x / CHUNKS;
    int chunk = blockIdx.x % CHUNKS;
    int w = threadIdx.x >> 5;
    int lane = threadIdx.x & 31;

    const float4* up = (const float4*)u + (size_t)b * NI * (NO * ND / 4);
    float acc[ND];
    float accden = 0.f;
#pragma unroll
    for (int d = 0; d < ND; d++) acc[d] = 0.f;

    int i0 = chunk * IPB + w * IPW;
    for (int ii = 0; ii < IPW; ii++) {
        const float4* row = up + (size_t)(i0 + ii) * (NO * ND / 4) + lane * (ND / 4);
        float4 a0 = row[0], a1 = row[1], a2 = row[2], a3 = row[3];
        float va[16] = {a0.x, a0.y, a0.z, a0.w, a1.x, a1.y, a1.z, a1.w,
                        a2.x, a2.y, a2.z, a2.w, a3.x, a3.y, a3.z, a3.w};
        float s = 0.f;
#pragma unroll
        for (int d = 0; d < 16; d++) s += va[d] * va[d];
        float n = sqrtf(s);
#pragma unroll
        for (int d = 0; d < 16; d++) acc[d] += va[d] * n;
        accden += n;
    }

    __shared__ float snum[8][NO * ND];
    __shared__ float sden[8][NO];
#pragma unroll
    for (int d = 0; d < ND; d++) snum[w][d * NO + lane] = acc[d];
    sden[w][lane] = accden;
    __syncthreads();

    for (int idx = threadIdx.x; idx < NO * ND; idx += 256) {
        int d = idx / NO, o = idx % NO;
        float s = 0.f;
#pragma unroll
        for (int ww = 0; ww < 8; ww++) s += snum[ww][idx];
        atomicAdd(&g_num[b * NO * ND + o * ND + d], s);
    }
    if (threadIdx.x < NO) {
        float s = 0.f;
#pragma unroll
        for (int ww = 0; ww < 8; ww++) s += sden[ww][threadIdx.x];
        atomicAdd(&g_den[b * NO + threadIdx.x], s);
    }
}

// ---------------------------------------------------------------------------
// Pass 2: losses[b,o,i] = -<v[b,o,:], u[b,i,o,:]>, v computed in-kernel.
// Stores TRANSPOSED [b][o][i] via padded smem tile for coalesced select reads.
// ---------------------------------------------------------------------------
__global__ void __launch_bounds__(256) k_pass2(const float* __restrict__ u) {
    __shared__ float sv[ND * NO];        // transposed: sv[d*NO + o]
    __shared__ float tile[IPB][NO + 1];  // [i_local][o], padded
    int b = blockIdx.x / CHUNKS;
    int chunk = blockIdx.x % CHUNKS;
    for (int idx = threadIdx.x; idx < NO * ND; idx += 256) {
        int o = idx / ND, d = idx % ND;
        sv[d * NO + o] = g_num[b * NO * ND + idx] / g_den[b * NO + o];
    }
    __syncthreads();

    int w = threadIdx.x >> 5;
    int lane = threadIdx.x & 31;
    const float4* up = (const float4*)u + (size_t)b * NI * (NO * ND / 4);
    int i0 = chunk * IPB;
    for (int ii = 0; ii < IPW; ii++) {
        int il = w * IPW + ii;
        const float4* row = up + (size_t)(i0 + il) * (NO * ND / 4) + lane * (ND / 4);
        float4 a0 = row[0], a1 = row[1], a2 = row[2], a3 = row[3];
        float va[16] = {a0.x, a0.y, a0.z, a0.w, a1.x, a1.y, a1.z, a1.w,
                        a2.x, a2.y, a2.z, a2.w, a3.x, a3.y, a3.z, a3.w};
        float dotv = 0.f;
#pragma unroll
        for (int d = 0; d < 16; d++) dotv += sv[d * NO + lane] * va[d];
        tile[il][lane] = -dotv;
    }
    __syncthreads();

    // Transposed, coalesced store: contiguous 512B per (o, i-block)
    for (int idx = threadIdx.x; idx < IPB * NO; idx += 256) {
        int o = idx >> 7;        // idx / 128
        int il = idx & 127;      // idx % 128
        g_losses[((size_t)(b * NO + o)) * NI + i0 + il] = tile[il][o];
    }
}

// ---------------------------------------------------------------------------
// Fused select + fixup: per (b,o) block.
//  1) radix-select (8 bits/round, 4 rounds) the KSUB-th smallest loss key
//  2) build rejected index list (key > thrkey) in smem
//  3) gather only the rejected capsules, subtract from totals, write output
// ---------------------------------------------------------------------------
__global__ void __launch_bounds__(256) k_selectfix(const float* __restrict__ u,
                                                  float* __restrict__ out) {
    __shared__ unsigned skey[NI];
    __shared__ int hist[256];
    __shared__ int srej[MAXREJ];
    __shared__ int scount;
    __shared__ int s_bucket, s_k;
    __shared__ float sred[8][17];
    __shared__ float stot[17];

    int b = blockIdx.x / NO;
    int o = blockIdx.x % NO;
    int tid = threadIdx.x;
    int w = tid >> 5, lane = tid & 31;

    // Load losses, convert to monotone unsigned keys
    const float* lp = &g_losses[((size_t)(b * NO + o)) * NI];
    for (int i = tid; i < NI; i += 256) {
        unsigned x = __float_as_uint(lp[i]);
        skey[i] = (x & 0x80000000u) ? ~x : (x | 0x80000000u);
    }
    if (tid == 0) scount = 0;
    __syncthreads();

    // Radix select, MSB-first, 8 bits per round
    unsigned prefix = 0;
    int k = KSUB;
    for (int shift = 24; shift >= 0; shift -= 8) {
        hist[tid] = 0;
        __syncthreads();
        for (int i = tid; i < NI; i += 256) {
            unsigned key = skey[i];
            bool match = (shift == 24) || ((key >> (shift + 8)) == (prefix >> (shift + 8)));
            if (match) atomicAdd(&hist[(key >> shift) & 255], 1);
        }
        __syncthreads();
        if (tid < 32) {
            int base = lane * 8;
            int h[8];
            int seg = 0;
#pragma unroll
            for (int j = 0; j < 8; j++) { h[j] = hist[base + j]; seg += h[j]; }
            int incl = seg;
            for (int off = 1; off < 32; off <<= 1) {
                int n_ = __shfl_up_sync(0xffffffffu, incl, off);
                if (lane >= off) incl += n_;
            }
            int excl = incl - seg;
            bool has = (excl < k) && (excl + seg >= k);
            unsigned m = __ballot_sync(0xffffffffu, has);
            int src = __ffs(m) - 1;
            if (lane == src) {
                int run = excl;
                int bsel = base, kk = k - excl;
#pragma unroll
                for (int j = 0; j < 8; j++) {
                    if (run + h[j] >= k) { bsel = base + j; kk = k - run; break; }
                    run += h[j];
                }
                s_bucket = bsel;
                s_k = kk;
            }
        }
        __syncthreads();
        prefix |= ((unsigned)s_bucket) << shift;
        k = s_k;
    }
    unsigned thrkey = prefix;

    // Build rejected list: key strictly greater than the k-th smallest
    for (int i = tid; i < NI; i += 256) {
        if (skey[i] > thrkey) {
            int p = atomicAdd(&scount, 1);
            srej[p] = i;
        }
    }
    __syncthreads();
    int nr = scount;  // <= NI - KSUB = 230

    // Gather rejected capsules, accumulate u*n and n
    float acc[16];
    float aden = 0.f;
#pragma unroll
    for (int d = 0; d < 16; d++) acc[d] = 0.f;
    const float4* up = (const float4*)u + (size_t)b * NI * (NO * ND / 4);
    for (int r = tid; r < nr; r += 256) {
        int i = srej[r];
        const float4* row = up + (size_t)i * (NO * ND / 4) + o * (ND / 4);
        float4 a0 = row[0], a1 = row[1], a2 = row[2], a3 = row[3];
        float va[16] = {a0.x, a0.y, a0.z, a0.w, a1.x, a1.y, a1.z, a1.w,
                        a2.x, a2.y, a2.z, a2.w, a3.x, a3.y, a3.z, a3.w};
        float s = 0.f;
#pragma unroll
        for (int d = 0; d < 16; d++) s += va[d] * va[d];
        float n = sqrtf(s);
#pragma unroll
        for (int d = 0; d < 16; d++) acc[d] += va[d] * n;
        aden += n;
    }

    // Reduce 17 values across the block
#pragma unroll
    for (int t = 0; t < 17; t++) {
        float v = (t < 16) ? acc[t] : aden;
        for (int off = 16; off > 0; off >>= 1)
            v += __shfl_down_sync(0xffffffffu, v, off);
        if (lane == 0) sred[w][t] = v;
    }
    __syncthreads();
    if (tid < 17) {
        float s = 0.f;
#pragma unroll
        for (int ww = 0; ww < 8; ww++) s += sred[ww][tid];
        stot[tid] = s;
    }
    __syncthreads();
    if (tid < 16) {
        float den2 = g_den[b * NO + o] - stot[16];
        out[(b * NO + o) * ND + tid] =
            (g_num[(b * NO + o) * ND + tid] - stot[tid]) / den2;
    }
}

extern "C" void kernel_launch(void* const* d_in, const int* in_sizes, int n_in,
                              void* d_out, int out_size) {
    const float* u = (const float*)d_in[0];
    float* out = (float*)d_out;

    k_zero<<<(NB * NO * ND + 255) / 256, 256>>>();
    k_pass1<<<NB * CHUNKS, 256>>>(u);
    k_pass2<<<NB * CHUNKS, 256>>>(u);
    k_selectfix<<<NB * NO, 256>>>(u, out);
}